// round 8
// baseline (speedup 1.0000x reference)
#include <cuda_runtime.h>
#include <cuda_fp16.h>
#include <cstdint>

#define MAX_NODES 100000
#define F_DIM     16
#define K_DIM     16
#define OUT_SCALE (1.0f / 128.0f)

// Yh[k][n][16] fp16 (51.2 MB)
__device__ __half g_Yh[(size_t)K_DIM * MAX_NODES * 16];

typedef unsigned long long ull;

// ---------- packed fp32x2 helpers (sm_100+ FFMA2) ----------
__device__ __forceinline__ ull pack2(float a, float b) {
    ull r;
    asm("mov.b64 %0, {%1, %2};" : "=l"(r) : "f"(a), "f"(b));
    return r;
}
__device__ __forceinline__ void fma2(ull& d, ull a, ull b) {
    asm("fma.rn.f32x2 %0, %1, %2, %3;" : "=l"(d) : "l"(a), "l"(b), "l"(d));
}
__device__ __forceinline__ void unpack2(ull v, float& a, float& b) {
    asm("mov.b64 {%0, %1}, %2;" : "=f"(a), "=f"(b) : "l"(v));
}
__device__ __forceinline__ float2 h2f(unsigned u) {
    __half2 h = *reinterpret_cast<__half2*>(&u);
    return __half22float2(h);
}

// ============================================================================
// Stage 1: Yh[k][n][:] = x[n] @ W[k].
// Grid (node_tiles, 4); blockIdx.y = block-uniform k-quad.
// R8 changes vs R6: x lives in SMEM ([i][tid], conflict-free) instead of 32
// registers (R4 showed regs=48 = acc+x2 exactly -> no headroom for ptxas to
// pipeline the W LDS chain -> ~28% issue). W(i+1) is explicitly prefetched
// during FMA(i) with the freed registers.
// ============================================================================
__global__ __launch_bounds__(256)
void stage1_kernel(const float* __restrict__ x,
                   const float* __restrict__ W,
                   int n_nodes) {
    __shared__ float Ws[4096];        // 16 KB W[k][i][o]
    __shared__ ull   xs2[16 * 256];   // 32 KB: xs2[i][tid] = (x,x)

    int tid = threadIdx.x;
    int node = blockIdx.x * 256 + tid;
    int kq = blockIdx.y * 4;

    for (int idx = tid; idx < 4096; idx += 256)
        Ws[idx] = W[idx];

    {
        int nclamp = min(node, n_nodes - 1);
        const float4* xp = reinterpret_cast<const float4*>(x + (size_t)nclamp * F_DIM);
#pragma unroll
        for (int q = 0; q < 4; q++) {
            float4 v = xp[q];
            xs2[(4 * q + 0) * 256 + tid] = pack2(v.x, v.x);
            xs2[(4 * q + 1) * 256 + tid] = pack2(v.y, v.y);
            xs2[(4 * q + 2) * 256 + tid] = pack2(v.z, v.z);
            xs2[(4 * q + 3) * 256 + tid] = pack2(v.w, v.w);
        }
    }
    __syncthreads();

    bool valid = (node < n_nodes);

#pragma unroll 1
    for (int kk = 0; kk < 4; kk++) {
        int k = kq + kk;
        const ulonglong2* wbase =
            reinterpret_cast<const ulonglong2*>(Ws + k * 256);

        ull acc0 = 0ull, acc1 = 0ull, acc2 = 0ull, acc3 = 0ull;
        ull acc4 = 0ull, acc5 = 0ull, acc6 = 0ull, acc7 = 0ull;

        // software-pipelined W: preload i=0
        ulonglong2 wa = wbase[0];
        ulonglong2 wb = wbase[1];
        ulonglong2 wc = wbase[2];
        ulonglong2 wd = wbase[3];

#pragma unroll
        for (int i = 0; i < F_DIM; i++) {
            ull xi = xs2[i * 256 + tid];
            ulonglong2 na, nb, nc, nd;
            if (i < F_DIM - 1) {
                na = wbase[(i + 1) * 4 + 0];
                nb = wbase[(i + 1) * 4 + 1];
                nc = wbase[(i + 1) * 4 + 2];
                nd = wbase[(i + 1) * 4 + 3];
            }
            fma2(acc0, xi, wa.x);
            fma2(acc1, xi, wa.y);
            fma2(acc2, xi, wb.x);
            fma2(acc3, xi, wb.y);
            fma2(acc4, xi, wc.x);
            fma2(acc5, xi, wc.y);
            fma2(acc6, xi, wd.x);
            fma2(acc7, xi, wd.y);
            if (i < F_DIM - 1) { wa = na; wb = nb; wc = nc; wd = nd; }
        }

        float o0, o1, o2, o3, o4, o5, o6, o7;
        float o8, o9, oa, ob, oc, od, oe, of_;
        unpack2(acc0, o0, o1); unpack2(acc1, o2, o3);
        unpack2(acc2, o4, o5); unpack2(acc3, o6, o7);
        unpack2(acc4, o8, o9); unpack2(acc5, oa, ob);
        unpack2(acc6, oc, od); unpack2(acc7, oe, of_);

        uint4 s0, s1;
        __half2 h;
        h = __floats2half2_rn(o0, o1); s0.x = *reinterpret_cast<unsigned*>(&h);
        h = __floats2half2_rn(o2, o3); s0.y = *reinterpret_cast<unsigned*>(&h);
        h = __floats2half2_rn(o4, o5); s0.z = *reinterpret_cast<unsigned*>(&h);
        h = __floats2half2_rn(o6, o7); s0.w = *reinterpret_cast<unsigned*>(&h);
        h = __floats2half2_rn(o8, o9); s1.x = *reinterpret_cast<unsigned*>(&h);
        h = __floats2half2_rn(oa, ob); s1.y = *reinterpret_cast<unsigned*>(&h);
        h = __floats2half2_rn(oc, od); s1.z = *reinterpret_cast<unsigned*>(&h);
        h = __floats2half2_rn(oe, of_); s1.w = *reinterpret_cast<unsigned*>(&h);

        if (valid) {
            uint4* yo = reinterpret_cast<uint4*>(
                g_Yh + ((size_t)k * n_nodes + node) * 16);
            yo[0] = s0;
            yo[1] = s1;
        }
    }
}

// ============================================================================
// Stage 2: per edge — bilinear combine of 4 fp16 Y blocks + atomic scatter
// (identical to the 42.4-42.8us kernel)
// ============================================================================
__global__ __launch_bounds__(256)
void stage2_kernel(const float2* __restrict__ edge_attr,
                   const int* __restrict__ ei,
                   const int* __restrict__ ej,
                   float* __restrict__ out,
                   int n_nodes, int n_edges) {
    int e = blockIdx.x * 256 + threadIdx.x;
    if (e >= n_edges) return;

    int di = ei[e];
    int dj = ej[e];
    if (di == dj) return;  // centerIgnore

    float2 at = edge_attr[e];
    float ux = fminf(fmaxf(at.x, -1.0f), 1.0f);
    float uy = fminf(fmaxf(at.y, -1.0f), 1.0f);
    float vx = (ux + 1.0f) * 1.5f;
    float vy = (uy + 1.0f) * 1.5f;
    int a = min((int)vx, 2);
    int b = min((int)vy, 2);
    float s = vx - (float)a;
    float t = vy - (float)b;

    float c00 = (1.0f - s) * (1.0f - t) * OUT_SCALE;
    float c01 = (1.0f - s) * t * OUT_SCALE;
    float c10 = s * (1.0f - t) * OUT_SCALE;
    float c11 = s * t * OUT_SCALE;

    int k00 = a * 4 + b;
    size_t row = (size_t)dj * 16;
    size_t kstride = (size_t)n_nodes * 16;
    const uint4* pA = reinterpret_cast<const uint4*>(g_Yh + (size_t)k00 * kstride + row);
    const uint4* pB = reinterpret_cast<const uint4*>(g_Yh + (size_t)(k00 + 1) * kstride + row);
    const uint4* pC = reinterpret_cast<const uint4*>(g_Yh + (size_t)(k00 + 4) * kstride + row);
    const uint4* pD = reinterpret_cast<const uint4*>(g_Yh + (size_t)(k00 + 5) * kstride + row);

    uint4 A0 = pA[0], A1 = pA[1];
    uint4 B0 = pB[0], B1 = pB[1];
    uint4 C0 = pC[0], C1 = pC[1];
    uint4 D0 = pD[0], D1 = pD[1];

    float* obase = out + (size_t)di * 16;

    {
        float2 fA, fB, fC, fD, m01, m23, m45, m67;
        fA = h2f(A0.x); fB = h2f(B0.x); fC = h2f(C0.x); fD = h2f(D0.x);
        m01.x = c00*fA.x + c01*fB.x + c10*fC.x + c11*fD.x;
        m01.y = c00*fA.y + c01*fB.y + c10*fC.y + c11*fD.y;
        fA = h2f(A0.y); fB = h2f(B0.y); fC = h2f(C0.y); fD = h2f(D0.y);
        m23.x = c00*fA.x + c01*fB.x + c10*fC.x + c11*fD.x;
        m23.y = c00*fA.y + c01*fB.y + c10*fC.y + c11*fD.y;
        fA = h2f(A0.z); fB = h2f(B0.z); fC = h2f(C0.z); fD = h2f(D0.z);
        m45.x = c00*fA.x + c01*fB.x + c10*fC.x + c11*fD.x;
        m45.y = c00*fA.y + c01*fB.y + c10*fC.y + c11*fD.y;
        fA = h2f(A0.w); fB = h2f(B0.w); fC = h2f(C0.w); fD = h2f(D0.w);
        m67.x = c00*fA.x + c01*fB.x + c10*fC.x + c11*fD.x;
        m67.y = c00*fA.y + c01*fB.y + c10*fC.y + c11*fD.y;
        asm volatile("red.global.add.v4.f32 [%0], {%1, %2, %3, %4};"
                     :: "l"(obase + 0), "f"(m01.x), "f"(m01.y), "f"(m23.x), "f"(m23.y)
                     : "memory");
        asm volatile("red.global.add.v4.f32 [%0], {%1, %2, %3, %4};"
                     :: "l"(obase + 4), "f"(m45.x), "f"(m45.y), "f"(m67.x), "f"(m67.y)
                     : "memory");
    }
    {
        float2 fA, fB, fC, fD, m01, m23, m45, m67;
        fA = h2f(A1.x); fB = h2f(B1.x); fC = h2f(C1.x); fD = h2f(D1.x);
        m01.x = c00*fA.x + c01*fB.x + c10*fC.x + c11*fD.x;
        m01.y = c00*fA.y + c01*fB.y + c10*fC.y + c11*fD.y;
        fA = h2f(A1.y); fB = h2f(B1.y); fC = h2f(C1.y); fD = h2f(D1.y);
        m23.x = c00*fA.x + c01*fB.x + c10*fC.x + c11*fD.x;
        m23.y = c00*fA.y + c01*fB.y + c10*fC.y + c11*fD.y;
        fA = h2f(A1.z); fB = h2f(B1.z); fC = h2f(C1.z); fD = h2f(D1.z);
        m45.x = c00*fA.x + c01*fB.x + c10*fC.x + c11*fD.x;
        m45.y = c00*fA.y + c01*fB.y + c10*fC.y + c11*fD.y;
        fA = h2f(A1.w); fB = h2f(B1.w); fC = h2f(C1.w); fD = h2f(D1.w);
        m67.x = c00*fA.x + c01*fB.x + c10*fC.x + c11*fD.x;
        m67.y = c00*fA.y + c01*fB.y + c10*fC.y + c11*fD.y;
        asm volatile("red.global.add.v4.f32 [%0], {%1, %2, %3, %4};"
                     :: "l"(obase + 8), "f"(m01.x), "f"(m01.y), "f"(m23.x), "f"(m23.y)
                     : "memory");
        asm volatile("red.global.add.v4.f32 [%0], {%1, %2, %3, %4};"
                     :: "l"(obase + 12), "f"(m45.x), "f"(m45.y), "f"(m67.x), "f"(m67.y)
                     : "memory");
    }
}

// Dummy kernel: shifts ncu's "-s 5 -c 1" alignment so the captured launch
// (#6) is replay-1's stage1 instead of stage2. Negligible cost.
__global__ void k_dummy() {}

extern "C" void kernel_launch(void* const* d_in, const int* in_sizes, int n_in,
                              void* d_out, int out_size) {
    const float*  x  = (const float*)d_in[0];    // [N, 16] f32
    const float2* ea = (const float2*)d_in[1];   // [E, 2]  f32
    const float*  W  = (const float*)d_in[2];    // [16,16,16] f32
    const int*    ei = (const int*)d_in[3];      // [E] int32
    const int*    ej = (const int*)d_in[4];      // [E] int32
    float* out = (float*)d_out;

    int n_nodes = in_sizes[0] / F_DIM;
    int n_edges = in_sizes[1] / 2;

    cudaMemsetAsync(d_out, 0, (size_t)out_size * sizeof(float), 0);

    dim3 s1grid((n_nodes + 255) / 256, 4);
    stage1_kernel<<<s1grid, 256>>>(x, W, n_nodes);
    stage2_kernel<<<(n_edges + 255) / 256, 256>>>(ea, ei, ej, out, n_nodes, n_edges);
    k_dummy<<<1, 32>>>();
}

// round 10
// speedup vs baseline: 1.1328x; 1.1328x over previous
#include <cuda_runtime.h>
#include <cuda_fp16.h>
#include <cstdint>

#define MAX_NODES 100000
#define F_DIM     16
#define K_DIM     16
#define OUT_SCALE (1.0f / 128.0f)

// Yh[k][n][16] fp16 (51.2 MB)
__device__ __half g_Yh[(size_t)K_DIM * MAX_NODES * 16];

typedef unsigned long long ull;

// ---------- packed fp32x2 helpers (sm_100+ FFMA2) ----------
__device__ __forceinline__ ull pack2(float a, float b) {
    ull r;
    asm("mov.b64 %0, {%1, %2};" : "=l"(r) : "f"(a), "f"(b));
    return r;
}
__device__ __forceinline__ void fma2(ull& d, ull a, ull b) {
    asm("fma.rn.f32x2 %0, %1, %2, %3;" : "=l"(d) : "l"(a), "l"(b), "l"(d));
}
__device__ __forceinline__ void unpack2(ull v, float& a, float& b) {
    asm("mov.b64 {%0, %1}, %2;" : "=f"(a), "=f"(b) : "l"(v));
}
__device__ __forceinline__ unsigned h2pack(float lo, float hi) {
    __half2 h = __floats2half2_rn(lo, hi);
    return *reinterpret_cast<unsigned*>(&h);
}
__device__ __forceinline__ float2 h2f(unsigned u) {
    __half2 h = *reinterpret_cast<__half2*>(&u);
    return __half22float2(h);
}

// ============================================================================
// Stage 1: Yh[k][n][:] = x[n] @ W[k]  (exact R3 version: ~37us measured; the
// tcgen05 path is unavailable — harness emits compute_103 PTX, no 'a' features)
// ============================================================================
__global__ __launch_bounds__(256)
void stage1_kernel(const float* __restrict__ x,
                   const float* __restrict__ W,
                   int n_nodes) {
    __shared__ float Ws[4096];
    for (int idx = threadIdx.x; idx < 4096; idx += 256)
        Ws[idx] = W[idx];
    __syncthreads();

    int node = blockIdx.x * 256 + threadIdx.x;
    if (node >= n_nodes) return;

    ull x2[16];
    const float4* xp = reinterpret_cast<const float4*>(x + (size_t)node * F_DIM);
#pragma unroll
    for (int q = 0; q < 4; q++) {
        float4 v = xp[q];
        x2[4 * q + 0] = pack2(v.x, v.x);
        x2[4 * q + 1] = pack2(v.y, v.y);
        x2[4 * q + 2] = pack2(v.z, v.z);
        x2[4 * q + 3] = pack2(v.w, v.w);
    }

#pragma unroll 1
    for (int k = 0; k < K_DIM; k++) {
        ull acc0 = 0ull, acc1 = 0ull, acc2 = 0ull, acc3 = 0ull;
        ull acc4 = 0ull, acc5 = 0ull, acc6 = 0ull, acc7 = 0ull;
        const ulonglong2* wbase =
            reinterpret_cast<const ulonglong2*>(Ws + k * 256);
#pragma unroll
        for (int i = 0; i < F_DIM; i++) {
            ulonglong2 wa = wbase[i * 4 + 0];
            ulonglong2 wb = wbase[i * 4 + 1];
            ulonglong2 wc = wbase[i * 4 + 2];
            ulonglong2 wd = wbase[i * 4 + 3];
            ull xi = x2[i];
            fma2(acc0, xi, wa.x);
            fma2(acc1, xi, wa.y);
            fma2(acc2, xi, wb.x);
            fma2(acc3, xi, wb.y);
            fma2(acc4, xi, wc.x);
            fma2(acc5, xi, wc.y);
            fma2(acc6, xi, wd.x);
            fma2(acc7, xi, wd.y);
        }
        float o0, o1, o2, o3, o4, o5, o6, o7;
        float o8, o9, oa, ob, oc, od, oe, of_;
        unpack2(acc0, o0, o1); unpack2(acc1, o2, o3);
        unpack2(acc2, o4, o5); unpack2(acc3, o6, o7);
        unpack2(acc4, o8, o9); unpack2(acc5, oa, ob);
        unpack2(acc6, oc, od); unpack2(acc7, oe, of_);

        uint4 s0, s1;
        s0.x = h2pack(o0, o1); s0.y = h2pack(o2, o3);
        s0.z = h2pack(o4, o5); s0.w = h2pack(o6, o7);
        s1.x = h2pack(o8, o9); s1.y = h2pack(oa, ob);
        s1.z = h2pack(oc, od); s1.w = h2pack(oe, of_);

        uint4* yo = reinterpret_cast<uint4*>(
            g_Yh + ((size_t)k * n_nodes + node) * 16);
        yo[0] = s0;
        yo[1] = s1;
    }
}

// ---------- per-edge combine helper (fp32) ----------
struct EdgeCoef { float c00, c01, c10, c11; };

__device__ __forceinline__ EdgeCoef make_coef(float ax, float ay, int& k00) {
    float ux = fminf(fmaxf(ax, -1.0f), 1.0f);
    float uy = fminf(fmaxf(ay, -1.0f), 1.0f);
    float vx = (ux + 1.0f) * 1.5f;
    float vy = (uy + 1.0f) * 1.5f;
    int a = min((int)vx, 2);
    int b = min((int)vy, 2);
    float s = vx - (float)a;
    float t = vy - (float)b;
    k00 = a * 4 + b;
    EdgeCoef c;
    c.c00 = (1.0f - s) * (1.0f - t) * OUT_SCALE;
    c.c01 = (1.0f - s) * t * OUT_SCALE;
    c.c10 = s * (1.0f - t) * OUT_SCALE;
    c.c11 = s * t * OUT_SCALE;
    return c;
}

__device__ __forceinline__ void combine_scatter(
    const uint4& A0, const uint4& A1, const uint4& B0, const uint4& B1,
    const uint4& C0, const uint4& C1, const uint4& D0, const uint4& D1,
    const EdgeCoef& c, float* obase) {
#pragma unroll
    for (int seg = 0; seg < 2; seg++) {
        const uint4& A = seg ? A1 : A0;
        const uint4& B = seg ? B1 : B0;
        const uint4& C = seg ? C1 : C0;
        const uint4& D = seg ? D1 : D0;
        float2 fA, fB, fC, fD;
        float m[8];
        fA = h2f(A.x); fB = h2f(B.x); fC = h2f(C.x); fD = h2f(D.x);
        m[0] = c.c00*fA.x + c.c01*fB.x + c.c10*fC.x + c.c11*fD.x;
        m[1] = c.c00*fA.y + c.c01*fB.y + c.c10*fC.y + c.c11*fD.y;
        fA = h2f(A.y); fB = h2f(B.y); fC = h2f(C.y); fD = h2f(D.y);
        m[2] = c.c00*fA.x + c.c01*fB.x + c.c10*fC.x + c.c11*fD.x;
        m[3] = c.c00*fA.y + c.c01*fB.y + c.c10*fC.y + c.c11*fD.y;
        fA = h2f(A.z); fB = h2f(B.z); fC = h2f(C.z); fD = h2f(D.z);
        m[4] = c.c00*fA.x + c.c01*fB.x + c.c10*fC.x + c.c11*fD.x;
        m[5] = c.c00*fA.y + c.c01*fB.y + c.c10*fC.y + c.c11*fD.y;
        fA = h2f(A.w); fB = h2f(B.w); fC = h2f(C.w); fD = h2f(D.w);
        m[6] = c.c00*fA.x + c.c01*fB.x + c.c10*fC.x + c.c11*fD.x;
        m[7] = c.c00*fA.y + c.c01*fB.y + c.c10*fC.y + c.c11*fD.y;
        asm volatile("red.global.add.v4.f32 [%0], {%1, %2, %3, %4};"
                     :: "l"(obase + seg * 8 + 0),
                        "f"(m[0]), "f"(m[1]), "f"(m[2]), "f"(m[3]) : "memory");
        asm volatile("red.global.add.v4.f32 [%0], {%1, %2, %3, %4};"
                     :: "l"(obase + seg * 8 + 4),
                        "f"(m[4]), "f"(m[5]), "f"(m[6]), "f"(m[7]) : "memory");
    }
}

// ============================================================================
// Stage 2: TWO edges per thread. All 16 Y LDG.128s are issued before any
// atomic (atomics' "memory" clobbers would otherwise fence the second edge's
// loads) -> ~2x memory-level parallelism per warp. R3 profile: issue=12%,
// occ=53% -> latency-bound, not byte-bound (L2 access floor ~29us).
// ============================================================================
__global__ __launch_bounds__(256, 2)
void stage2_pair(const float4* __restrict__ ea4,   // 2 edges per float4
                 const int2* __restrict__ ei2,
                 const int2* __restrict__ ej2,
                 float* __restrict__ out,
                 int n_nodes, int n_pairs, int n_edges) {
    int p = blockIdx.x * 256 + threadIdx.x;
    if (p >= n_pairs) return;

    int2 I = ei2[p];
    int2 J = ej2[p];
    float4 at = ea4[p];

    int eA = 2 * p, eB = 2 * p + 1;
    bool vA = (eA < n_edges) && (I.x != J.x);
    bool vB = (eB < n_edges) && (I.y != J.y);

    size_t kstride = (size_t)n_nodes * 16;

    EdgeCoef cA, cB;
    int kA = 0, kB = 0;
    uint4 A0a, A1a, B0a, B1a, C0a, C1a, D0a, D1a;
    uint4 A0b, A1b, B0b, B1b, C0b, C1b, D0b, D1b;

    if (vA) {
        cA = make_coef(at.x, at.y, kA);
        const __half* yb = g_Yh + (size_t)kA * kstride + (size_t)J.x * 16;
        const uint4* pA = reinterpret_cast<const uint4*>(yb);
        const uint4* pB = reinterpret_cast<const uint4*>(yb + kstride);
        const uint4* pC = reinterpret_cast<const uint4*>(yb + 4 * kstride);
        const uint4* pD = reinterpret_cast<const uint4*>(yb + 5 * kstride);
        A0a = pA[0]; A1a = pA[1]; B0a = pB[0]; B1a = pB[1];
        C0a = pC[0]; C1a = pC[1]; D0a = pD[0]; D1a = pD[1];
    }
    if (vB) {
        cB = make_coef(at.z, at.w, kB);
        const __half* yb = g_Yh + (size_t)kB * kstride + (size_t)J.y * 16;
        const uint4* pA = reinterpret_cast<const uint4*>(yb);
        const uint4* pB = reinterpret_cast<const uint4*>(yb + kstride);
        const uint4* pC = reinterpret_cast<const uint4*>(yb + 4 * kstride);
        const uint4* pD = reinterpret_cast<const uint4*>(yb + 5 * kstride);
        A0b = pA[0]; A1b = pA[1]; B0b = pB[0]; B1b = pB[1];
        C0b = pC[0]; C1b = pC[1]; D0b = pD[0]; D1b = pD[1];
    }

    if (vA)
        combine_scatter(A0a, A1a, B0a, B1a, C0a, C1a, D0a, D1a,
                        cA, out + (size_t)I.x * 16);
    if (vB)
        combine_scatter(A0b, A1b, B0b, B1b, C0b, C1b, D0b, D1b,
                        cB, out + (size_t)I.y * 16);
}

extern "C" void kernel_launch(void* const* d_in, const int* in_sizes, int n_in,
                              void* d_out, int out_size) {
    const float*  x  = (const float*)d_in[0];    // [N, 16] f32
    const float4* ea = (const float4*)d_in[1];   // [E, 2]  f32 (paired)
    const float*  W  = (const float*)d_in[2];    // [16,16,16] f32
    const int2*   ei = (const int2*)d_in[3];     // [E] int32 (paired)
    const int2*   ej = (const int2*)d_in[4];
    float* out = (float*)d_out;

    int n_nodes = in_sizes[0] / F_DIM;
    int n_edges = in_sizes[1] / 2;
    int n_pairs = (n_edges + 1) / 2;

    cudaMemsetAsync(d_out, 0, (size_t)out_size * sizeof(float), 0);

    stage1_kernel<<<(n_nodes + 255) / 256, 256>>>(x, W, n_nodes);
    stage2_pair<<<(n_pairs + 255) / 256, 256>>>(ea, ei, ej, out,
                                                n_nodes, n_pairs, n_edges);
}

// round 11
// speedup vs baseline: 1.1418x; 1.0080x over previous
#include <cuda_runtime.h>
#include <cuda_fp16.h>
#include <cstdint>

#define MAX_NODES 100000
#define F_DIM     16
#define K_DIM     16
#define OUT_SCALE (1.0f / 128.0f)

// Yh[k][n][16] fp16 (51.2 MB)
__device__ __half g_Yh[(size_t)K_DIM * MAX_NODES * 16];

typedef unsigned long long ull;

// ---------- packed fp32x2 helpers ----------
__device__ __forceinline__ ull pack2(float a, float b) {
    ull r;
    asm("mov.b64 %0, {%1, %2};" : "=l"(r) : "f"(a), "f"(b));
    return r;
}
__device__ __forceinline__ void fma2(ull& d, ull a, ull b) {
    asm("fma.rn.f32x2 %0, %1, %2, %3;" : "=l"(d) : "l"(a), "l"(b), "l"(d));
}
__device__ __forceinline__ void unpack2(ull v, float& a, float& b) {
    asm("mov.b64 {%0, %1}, %2;" : "=f"(a), "=f"(b) : "l"(v));
}
__device__ __forceinline__ unsigned h2pack(float lo, float hi) {
    __half2 h = __floats2half2_rn(lo, hi);
    return *reinterpret_cast<unsigned*>(&h);
}
__device__ __forceinline__ float2 h2f(unsigned u) {
    __half2 h = *reinterpret_cast<__half2*>(&u);
    return __half22float2(h);
}

// ============================================================================
// Stage 1: Yh[k][n][:] = x[n] @ W[k]  (best-known R3 version, ~37us)
// ============================================================================
__global__ __launch_bounds__(256)
void stage1_kernel(const float* __restrict__ x,
                   const float* __restrict__ W,
                   int n_nodes) {
    __shared__ float Ws[4096];
    for (int idx = threadIdx.x; idx < 4096; idx += 256)
        Ws[idx] = W[idx];
    __syncthreads();

    int node = blockIdx.x * 256 + threadIdx.x;
    if (node >= n_nodes) return;

    ull x2[16];
    const float4* xp = reinterpret_cast<const float4*>(x + (size_t)node * F_DIM);
#pragma unroll
    for (int q = 0; q < 4; q++) {
        float4 v = xp[q];
        x2[4 * q + 0] = pack2(v.x, v.x);
        x2[4 * q + 1] = pack2(v.y, v.y);
        x2[4 * q + 2] = pack2(v.z, v.z);
        x2[4 * q + 3] = pack2(v.w, v.w);
    }

#pragma unroll 1
    for (int k = 0; k < K_DIM; k++) {
        ull acc0 = 0ull, acc1 = 0ull, acc2 = 0ull, acc3 = 0ull;
        ull acc4 = 0ull, acc5 = 0ull, acc6 = 0ull, acc7 = 0ull;
        const ulonglong2* wbase =
            reinterpret_cast<const ulonglong2*>(Ws + k * 256);
#pragma unroll
        for (int i = 0; i < F_DIM; i++) {
            ulonglong2 wa = wbase[i * 4 + 0];
            ulonglong2 wb = wbase[i * 4 + 1];
            ulonglong2 wc = wbase[i * 4 + 2];
            ulonglong2 wd = wbase[i * 4 + 3];
            ull xi = x2[i];
            fma2(acc0, xi, wa.x);
            fma2(acc1, xi, wa.y);
            fma2(acc2, xi, wb.x);
            fma2(acc3, xi, wb.y);
            fma2(acc4, xi, wc.x);
            fma2(acc5, xi, wc.y);
            fma2(acc6, xi, wd.x);
            fma2(acc7, xi, wd.y);
        }
        float o0, o1, o2, o3, o4, o5, o6, o7;
        float o8, o9, oa, ob, oc, od, oe, of_;
        unpack2(acc0, o0, o1); unpack2(acc1, o2, o3);
        unpack2(acc2, o4, o5); unpack2(acc3, o6, o7);
        unpack2(acc4, o8, o9); unpack2(acc5, oa, ob);
        unpack2(acc6, oc, od); unpack2(acc7, oe, of_);

        uint4 s0, s1;
        s0.x = h2pack(o0, o1); s0.y = h2pack(o2, o3);
        s0.z = h2pack(o4, o5); s0.w = h2pack(o6, o7);
        s1.x = h2pack(o8, o9); s1.y = h2pack(oa, ob);
        s1.z = h2pack(oc, od); s1.w = h2pack(oe, of_);

        uint4* yo = reinterpret_cast<uint4*>(
            g_Yh + ((size_t)k * n_nodes + node) * 16);
        yo[0] = s0;
        yo[1] = s1;
    }
}

// ============================================================================
// Stage 2 (warp-cooperative): 8 lanes per edge.
// lane = 8*g + r;  r: block b=r>>1 in {k00,k00+1,k00+4,k00+5}, segment s=r&1.
// One LDG.128/lane fetches the edge's whole 128B; both segments of a block
// share one 128B line -> 4 lines/edge (vs 8 with thread-per-edge) -> halves
// the gather wavefronts that bind this kernel (wf model matches R3/R6/R10:
// 12 wf/edge ~= 37-43us).  shfl.bfly (masks 2,4) sums across blocks; lanes
// r<2 issue the 4 atomics.
// ============================================================================
__global__ __launch_bounds__(256)
void stage2_coop(const float2* __restrict__ edge_attr,
                 const int* __restrict__ ei,
                 const int* __restrict__ ej,
                 float* __restrict__ out,
                 int n_nodes, int n_edges) {
    const unsigned FULL = 0xFFFFFFFFu;
    int lane = threadIdx.x & 31;
    int gwarp = (blockIdx.x * 256 + threadIdx.x) >> 5;
    int g = lane >> 3;          // edge slot within warp (0..3)
    int r = lane & 7;
    int b = r >> 1;             // block 0..3
    int s = r & 1;              // 16B segment
    size_t kstride = (size_t)n_nodes * 16;

    int ebase = gwarp * 16;     // 16 edges per warp (4 iters x 4 edges)
    if (ebase >= n_edges) return;

#pragma unroll 1
    for (int it = 0; it < 4; it++) {
        int e = ebase + it * 4 + g;
        bool val = (e < n_edges);
        int eL = val ? e : 0;

        int di = ei[eL];
        int dj = ej[eL];
        float2 at = edge_attr[eL];
        val = val && (di != dj);

        // bilinear cell + per-block coefficient (lane computes only its own)
        float ux = fminf(fmaxf(at.x, -1.0f), 1.0f);
        float uy = fminf(fmaxf(at.y, -1.0f), 1.0f);
        float vx = (ux + 1.0f) * 1.5f;
        float vy = (uy + 1.0f) * 1.5f;
        int ca = min((int)vx, 2);
        int cb_ = min((int)vy, 2);
        float sx = vx - (float)ca;
        float ty = vy - (float)cb_;
        int k00 = ca * 4 + cb_;

        float cf = ((b & 2) ? sx : (1.0f - sx)) *
                   ((b & 1) ? ty : (1.0f - ty)) * OUT_SCALE;
        if (!val) cf = 0.0f;
        int djs = val ? dj : 0;

        int k = k00 + ((b & 2) << 1) + (b & 1);   // {0,1,4,5} offsets
        const uint4* p = reinterpret_cast<const uint4*>(
            g_Yh + (size_t)k * kstride + (size_t)djs * 16 + s * 8);
        uint4 Y = *p;

        float2 f0 = h2f(Y.x), f1 = h2f(Y.y), f2 = h2f(Y.z), f3 = h2f(Y.w);
        float m0 = cf * f0.x, m1 = cf * f0.y;
        float m2 = cf * f1.x, m3 = cf * f1.y;
        float m4 = cf * f2.x, m5 = cf * f2.y;
        float m6 = cf * f3.x, m7 = cf * f3.y;

        // reduce across the 4 blocks (lanes differing in bits 1,2)
        m0 += __shfl_xor_sync(FULL, m0, 2); m0 += __shfl_xor_sync(FULL, m0, 4);
        m1 += __shfl_xor_sync(FULL, m1, 2); m1 += __shfl_xor_sync(FULL, m1, 4);
        m2 += __shfl_xor_sync(FULL, m2, 2); m2 += __shfl_xor_sync(FULL, m2, 4);
        m3 += __shfl_xor_sync(FULL, m3, 2); m3 += __shfl_xor_sync(FULL, m3, 4);
        m4 += __shfl_xor_sync(FULL, m4, 2); m4 += __shfl_xor_sync(FULL, m4, 4);
        m5 += __shfl_xor_sync(FULL, m5, 2); m5 += __shfl_xor_sync(FULL, m5, 4);
        m6 += __shfl_xor_sync(FULL, m6, 2); m6 += __shfl_xor_sync(FULL, m6, 4);
        m7 += __shfl_xor_sync(FULL, m7, 2); m7 += __shfl_xor_sync(FULL, m7, 4);

        // lanes r=0 (segment halves 0..7) and r=1 (halves 8..15) scatter
        if (r < 2 && val) {
            float* ob = out + (size_t)di * 16 + r * 8;
            asm volatile("red.global.add.v4.f32 [%0], {%1, %2, %3, %4};"
                         :: "l"(ob), "f"(m0), "f"(m1), "f"(m2), "f"(m3)
                         : "memory");
            asm volatile("red.global.add.v4.f32 [%0], {%1, %2, %3, %4};"
                         :: "l"(ob + 4), "f"(m4), "f"(m5), "f"(m6), "f"(m7)
                         : "memory");
        }
    }
}

extern "C" void kernel_launch(void* const* d_in, const int* in_sizes, int n_in,
                              void* d_out, int out_size) {
    const float*  x  = (const float*)d_in[0];    // [N, 16] f32
    const float2* ea = (const float2*)d_in[1];   // [E, 2]  f32
    const float*  W  = (const float*)d_in[2];    // [16,16,16] f32
    const int*    ei = (const int*)d_in[3];      // [E] int32
    const int*    ej = (const int*)d_in[4];      // [E] int32
    float* out = (float*)d_out;

    int n_nodes = in_sizes[0] / F_DIM;
    int n_edges = in_sizes[1] / 2;

    cudaMemsetAsync(d_out, 0, (size_t)out_size * sizeof(float), 0);

    stage1_kernel<<<(n_nodes + 255) / 256, 256>>>(x, W, n_nodes);

    // 16 edges per warp, 8 warps per block -> 128 edges per block
    int s2_blocks = (n_edges + 127) / 128;
    stage2_coop<<<s2_blocks, 256>>>(ea, ei, ej, out, n_nodes, n_edges);
}

// round 12
// speedup vs baseline: 1.3556x; 1.1873x over previous
#include <cuda_runtime.h>
#include <cuda_fp16.h>
#include <cstdint>

#define MAX_NODES 100000
#define F_DIM     16
#define K_DIM     16
#define OUT_SCALE (1.0f / 128.0f)

// Yh[k][n][16] fp16 (51.2 MB)
__device__ __half g_Yh[(size_t)K_DIM * MAX_NODES * 16];

typedef unsigned long long ull;

// ---------- packed fp32x2 helpers ----------
__device__ __forceinline__ ull pack2(float a, float b) {
    ull r;
    asm("mov.b64 %0, {%1, %2};" : "=l"(r) : "f"(a), "f"(b));
    return r;
}
__device__ __forceinline__ void fma2(ull& d, ull a, ull b) {
    asm("fma.rn.f32x2 %0, %1, %2, %3;" : "=l"(d) : "l"(a), "l"(b), "l"(d));
}
__device__ __forceinline__ void unpack2(ull v, float& a, float& b) {
    asm("mov.b64 {%0, %1}, %2;" : "=f"(a), "=f"(b) : "l"(v));
}
__device__ __forceinline__ unsigned h2pack(float lo, float hi) {
    __half2 h = __floats2half2_rn(lo, hi);
    return *reinterpret_cast<unsigned*>(&h);
}
__device__ __forceinline__ float2 h2f(unsigned u) {
    __half2 h = *reinterpret_cast<__half2*>(&u);
    return __half22float2(h);
}

// ============================================================================
// Stage 1 (column-owner): thread owns (k, o-quad); its 64 W floats live in 32
// ull REGISTERS loaded once from global. Eliminates the 16x-redundant 16KB
// W smem re-read that bound all prior stage1 variants (~1024 LDS.128/thread).
// Block: 256 thr = 4 subgroups x 64 columns; 128-node tile; subgroup sg
// processes nodes {4j+sg}. x pairs in smem, warp-uniform LDS.64 reads.
// ============================================================================
__global__ __launch_bounds__(256)
void stage1_cols(const float* __restrict__ x,
                 const float* __restrict__ W,
                 int n_nodes) {
    __shared__ ull xs2[128 * 16];   // 16 KB: xs2[node_local][i] = (x,x)

    int tid = threadIdx.x;
    int col = tid & 63;             // 0..63
    int sg  = tid >> 6;             // 0..3
    int k   = col >> 2;             // 0..15
    int oq  = (col & 3) * 4;        // 0,4,8,12
    int node_base = blockIdx.x * 128;

    // W columns to registers (once)
    ull w0[16], w1[16];
#pragma unroll
    for (int i = 0; i < 16; i++) {
        float4 wv = *reinterpret_cast<const float4*>(W + k * 256 + i * 16 + oq);
        w0[i] = pack2(wv.x, wv.y);
        w1[i] = pack2(wv.z, wv.w);
    }

    // x tile -> smem pairs
    for (int idx = tid; idx < 128 * 4; idx += 256) {
        int n = idx >> 2, q = idx & 3;
        int node = min(node_base + n, n_nodes - 1);
        float4 v = reinterpret_cast<const float4*>(x + (size_t)node * 16)[q];
        ull* dst = xs2 + n * 16 + q * 4;
        dst[0] = pack2(v.x, v.x);
        dst[1] = pack2(v.y, v.y);
        dst[2] = pack2(v.z, v.z);
        dst[3] = pack2(v.w, v.w);
    }
    __syncthreads();

#pragma unroll 1
    for (int j = 0; j < 32; j++) {
        int nl = j * 4 + sg;
        int node = node_base + nl;
        const ull* xp = xs2 + nl * 16;
        ull a0 = 0ull, a1 = 0ull;
#pragma unroll
        for (int i = 0; i < 16; i++) {
            ull xi = xp[i];           // warp-uniform broadcast
            fma2(a0, xi, w0[i]);
            fma2(a1, xi, w1[i]);
        }
        if (node < n_nodes) {
            float p0, p1, p2, p3;
            unpack2(a0, p0, p1);
            unpack2(a1, p2, p3);
            unsigned h01 = h2pack(p0, p1);
            unsigned h23 = h2pack(p2, p3);
            ull payload;
            asm("mov.b64 %0, {%1, %2};" : "=l"(payload) : "r"(h01), "r"(h23));
            *reinterpret_cast<ull*>(
                g_Yh + ((size_t)k * n_nodes + node) * 16 + oq) = payload;
        }
    }
}

// ============================================================================
// Stage 2 (warp-coop + reduce-scatter): 8 lanes/edge as in R11, but the
// cross-block reduction is a value-splitting butterfly: 6 SHFLs (vs 16) and
// every lane finishes with 2 output floats -> ONE red.v2.f32 warp-instruction
// covering 4 contiguous 64B rows. R11 profile: issue=52%, alu=fma=22.6% ->
// instruction-bound; this cuts per-edge issue count ~35%.
// ============================================================================
__global__ __launch_bounds__(256)
void stage2_coop(const float2* __restrict__ edge_attr,
                 const int* __restrict__ ei,
                 const int* __restrict__ ej,
                 float* __restrict__ out,
                 int n_nodes, int n_edges) {
    const unsigned FULL = 0xFFFFFFFFu;
    int lane = threadIdx.x & 31;
    int gwarp = (blockIdx.x * 256 + threadIdx.x) >> 5;
    int g = lane >> 3;          // edge slot (0..3)
    int r = lane & 7;
    int b = r >> 1;             // block 0..3
    int s = r & 1;              // 16B segment
    size_t kstride = (size_t)n_nodes * 16;

    int ebase = gwarp * 16;
    if (ebase >= n_edges) return;

    bool keep1 = (b & 1) == 0;  // round-1 keeps chunk [0..3]
    bool keep2 = (b & 2) == 0;  // round-2 keeps sub [0..1]

#pragma unroll 1
    for (int it = 0; it < 4; it++) {
        int e = ebase + it * 4 + g;
        bool val = (e < n_edges);
        int eL = val ? e : 0;

        int di = ei[eL];
        int dj = ej[eL];
        float2 at = edge_attr[eL];
        val = val && (di != dj);

        float ux = fminf(fmaxf(at.x, -1.0f), 1.0f);
        float uy = fminf(fmaxf(at.y, -1.0f), 1.0f);
        float vx = (ux + 1.0f) * 1.5f;
        float vy = (uy + 1.0f) * 1.5f;
        int ca = min((int)vx, 2);
        int cb_ = min((int)vy, 2);
        float sx = vx - (float)ca;
        float ty = vy - (float)cb_;
        int k00 = ca * 4 + cb_;

        float cf = ((b & 2) ? sx : (1.0f - sx)) *
                   ((b & 1) ? ty : (1.0f - ty)) * OUT_SCALE;
        if (!val) cf = 0.0f;
        int djs = val ? dj : 0;

        int k = k00 + ((b & 2) << 1) + (b & 1);   // +{0,1,4,5}
        const uint4* p = reinterpret_cast<const uint4*>(
            g_Yh + (size_t)k * kstride + (size_t)djs * 16 + s * 8);
        uint4 Y = *p;

        float2 f0 = h2f(Y.x), f1 = h2f(Y.y), f2 = h2f(Y.z), f3 = h2f(Y.w);
        float m0 = cf * f0.x, m1 = cf * f0.y;
        float m2 = cf * f1.x, m3 = cf * f1.y;
        float m4 = cf * f2.x, m5 = cf * f2.y;
        float m6 = cf * f3.x, m7 = cf * f3.y;

        // Round 1 (mask 2): keep 4-chunk, send the other
        float s0_ = keep1 ? m4 : m0;
        float s1_ = keep1 ? m5 : m1;
        float s2_ = keep1 ? m6 : m2;
        float s3_ = keep1 ? m7 : m3;
        float p0 = (keep1 ? m0 : m4) + __shfl_xor_sync(FULL, s0_, 2);
        float p1 = (keep1 ? m1 : m5) + __shfl_xor_sync(FULL, s1_, 2);
        float p2 = (keep1 ? m2 : m6) + __shfl_xor_sync(FULL, s2_, 2);
        float p3 = (keep1 ? m3 : m7) + __shfl_xor_sync(FULL, s3_, 2);

        // Round 2 (mask 4): keep 2-sub, send the other
        float t0 = keep2 ? p2 : p0;
        float t1 = keep2 ? p3 : p1;
        float q0 = (keep2 ? p0 : p2) + __shfl_xor_sync(FULL, t0, 4);
        float q1 = (keep2 ? p1 : p3) + __shfl_xor_sync(FULL, t1, 4);

        // lane holds floats [idx, idx+1] of out row di
        if (val) {
            int idx = s * 8 + (b & 1) * 4 + ((b >> 1) & 1) * 2;
            float* ob = out + (size_t)di * 16 + idx;
            asm volatile("red.global.add.v2.f32 [%0], {%1, %2};"
                         :: "l"(ob), "f"(q0), "f"(q1) : "memory");
        }
    }
}

// Aligns ncu capture (-s 5 -c 1) onto stage1 (4 launches/call)
__global__ void k_dummy() {}

extern "C" void kernel_launch(void* const* d_in, const int* in_sizes, int n_in,
                              void* d_out, int out_size) {
    const float*  x  = (const float*)d_in[0];    // [N, 16] f32
    const float2* ea = (const float2*)d_in[1];   // [E, 2]  f32
    const float*  W  = (const float*)d_in[2];    // [16,16,16] f32
    const int*    ei = (const int*)d_in[3];      // [E] int32
    const int*    ej = (const int*)d_in[4];      // [E] int32
    float* out = (float*)d_out;

    int n_nodes = in_sizes[0] / F_DIM;
    int n_edges = in_sizes[1] / 2;

    cudaMemsetAsync(d_out, 0, (size_t)out_size * sizeof(float), 0);

    stage1_cols<<<(n_nodes + 127) / 128, 256>>>(x, W, n_nodes);

    int s2_blocks = (n_edges + 127) / 128;
    stage2_coop<<<s2_blocks, 256>>>(ea, ei, ej, out, n_nodes, n_edges);
    k_dummy<<<1, 32>>>();
}

// round 13
// speedup vs baseline: 1.3610x; 1.0040x over previous
#include <cuda_runtime.h>
#include <cuda_fp16.h>
#include <cstdint>

#define MAX_NODES 100000
#define F_DIM     16
#define K_DIM     16
#define OUT_SCALE (1.0f / 128.0f)

// Yh[k][n][16] fp16 (51.2 MB)
__device__ __half g_Yh[(size_t)K_DIM * MAX_NODES * 16];

typedef unsigned long long ull;

// ---------- packed fp32x2 helpers ----------
__device__ __forceinline__ ull pack2(float a, float b) {
    ull r;
    asm("mov.b64 %0, {%1, %2};" : "=l"(r) : "f"(a), "f"(b));
    return r;
}
__device__ __forceinline__ void fma2(ull& d, ull a, ull b) {
    asm("fma.rn.f32x2 %0, %1, %2, %3;" : "=l"(d) : "l"(a), "l"(b), "l"(d));
}
__device__ __forceinline__ void unpack2(ull v, float& a, float& b) {
    asm("mov.b64 {%0, %1}, %2;" : "=f"(a), "=f"(b) : "l"(v));
}
__device__ __forceinline__ unsigned h2pack(float lo, float hi) {
    __half2 h = __floats2half2_rn(lo, hi);
    return *reinterpret_cast<unsigned*>(&h);
}
__device__ __forceinline__ float2 h2f(unsigned u) {
    __half2 h = *reinterpret_cast<__half2*>(&u);
    return __half22float2(h);
}

// ============================================================================
// Stage 1 (column-owner v2): thread owns (k, o-quad), W in 32 ull regs.
// R13 vs R12: (a) x read as LDS.128 (2 i-pairs/inst, 8 loads/node vs 16);
// (b) TWO nodes in flight (j-unroll 2, dual acc pairs) so FMA2 pipe work
// (128 cyc) exceeds issue demand; (c) 64-node tiles -> 1564 blocks;
// (d) strength-reduced Y store addressing.
// R12 profile: occ 22.7 (regs=98, 2 blk/SM), issue 43, fma 33, alu 13.6.
// ============================================================================
__global__ __launch_bounds__(256)
void stage1_cols(const float* __restrict__ x,
                 const float* __restrict__ W,
                 int n_nodes) {
    __shared__ ull xs2[64 * 16];    // 8 KB: xs2[node_local][i] = (x,x)

    int tid = threadIdx.x;
    int col = tid & 63;             // 0..63
    int sg  = tid >> 6;             // 0..3 (warp-uniform)
    int k   = col >> 2;             // 0..15
    int oq  = (col & 3) * 4;        // 0,4,8,12
    int node_base = blockIdx.x * 64;

    // W columns to registers (once per block-life)
    ull w0[16], w1[16];
#pragma unroll
    for (int i = 0; i < 16; i++) {
        float4 wv = *reinterpret_cast<const float4*>(W + k * 256 + i * 16 + oq);
        w0[i] = pack2(wv.x, wv.y);
        w1[i] = pack2(wv.z, wv.w);
    }

    // x tile -> smem pairs
    for (int idx = tid; idx < 64 * 4; idx += 256) {
        int n = idx >> 2, q = idx & 3;
        int node = min(node_base + n, n_nodes - 1);
        float4 v = reinterpret_cast<const float4*>(x + (size_t)node * 16)[q];
        ull* dst = xs2 + n * 16 + q * 4;
        dst[0] = pack2(v.x, v.x);
        dst[1] = pack2(v.y, v.y);
        dst[2] = pack2(v.z, v.z);
        dst[3] = pack2(v.w, v.w);
    }
    __syncthreads();

    // Strength-reduced store pointer: row (k, node_base+sg), advances 4 rows/j
    __half* ybase = g_Yh + ((size_t)k * n_nodes + node_base + sg) * 16 + oq;

#pragma unroll 1
    for (int j = 0; j < 16; j += 2) {
        int nlA = j * 4 + sg;
        const ulonglong2* xpA = reinterpret_cast<const ulonglong2*>(xs2 + nlA * 16);
        const ulonglong2* xpB = reinterpret_cast<const ulonglong2*>(xs2 + (nlA + 4) * 16);

        ull a0 = 0ull, a1 = 0ull, b0 = 0ull, b1 = 0ull;
#pragma unroll
        for (int i2 = 0; i2 < 8; i2++) {
            ulonglong2 xA = xpA[i2];   // (x_{2i2},x_{2i2}),(x_{2i2+1},..)
            ulonglong2 xB = xpB[i2];
            fma2(a0, xA.x, w0[2 * i2]);
            fma2(a1, xA.x, w1[2 * i2]);
            fma2(b0, xB.x, w0[2 * i2]);
            fma2(b1, xB.x, w1[2 * i2]);
            fma2(a0, xA.y, w0[2 * i2 + 1]);
            fma2(a1, xA.y, w1[2 * i2 + 1]);
            fma2(b0, xB.y, w0[2 * i2 + 1]);
            fma2(b1, xB.y, w1[2 * i2 + 1]);
        }

        int nodeA = node_base + nlA;
        if (nodeA < n_nodes) {
            float p0, p1, p2, p3;
            unpack2(a0, p0, p1);
            unpack2(a1, p2, p3);
            unsigned h01 = h2pack(p0, p1), h23 = h2pack(p2, p3);
            ull payload;
            asm("mov.b64 %0, {%1, %2};" : "=l"(payload) : "r"(h01), "r"(h23));
            *reinterpret_cast<ull*>(ybase + (size_t)j * 64) = payload;
        }
        if (nodeA + 4 < n_nodes) {
            float p0, p1, p2, p3;
            unpack2(b0, p0, p1);
            unpack2(b1, p2, p3);
            unsigned h01 = h2pack(p0, p1), h23 = h2pack(p2, p3);
            ull payload;
            asm("mov.b64 %0, {%1, %2};" : "=l"(payload) : "r"(h01), "r"(h23));
            *reinterpret_cast<ull*>(ybase + (size_t)(j + 1) * 64) = payload;
        }
    }
}

// ============================================================================
// Stage 2 (warp-coop + reduce-scatter butterfly) — frozen at R12 (~29us)
// ============================================================================
__global__ __launch_bounds__(256)
void stage2_coop(const float2* __restrict__ edge_attr,
                 const int* __restrict__ ei,
                 const int* __restrict__ ej,
                 float* __restrict__ out,
                 int n_nodes, int n_edges) {
    const unsigned FULL = 0xFFFFFFFFu;
    int lane = threadIdx.x & 31;
    int gwarp = (blockIdx.x * 256 + threadIdx.x) >> 5;
    int g = lane >> 3;
    int r = lane & 7;
    int b = r >> 1;
    int s = r & 1;
    size_t kstride = (size_t)n_nodes * 16;

    int ebase = gwarp * 16;
    if (ebase >= n_edges) return;

    bool keep1 = (b & 1) == 0;
    bool keep2 = (b & 2) == 0;

#pragma unroll 1
    for (int it = 0; it < 4; it++) {
        int e = ebase + it * 4 + g;
        bool val = (e < n_edges);
        int eL = val ? e : 0;

        int di = ei[eL];
        int dj = ej[eL];
        float2 at = edge_attr[eL];
        val = val && (di != dj);

        float ux = fminf(fmaxf(at.x, -1.0f), 1.0f);
        float uy = fminf(fmaxf(at.y, -1.0f), 1.0f);
        float vx = (ux + 1.0f) * 1.5f;
        float vy = (uy + 1.0f) * 1.5f;
        int ca = min((int)vx, 2);
        int cb_ = min((int)vy, 2);
        float sx = vx - (float)ca;
        float ty = vy - (float)cb_;
        int k00 = ca * 4 + cb_;

        float cf = ((b & 2) ? sx : (1.0f - sx)) *
                   ((b & 1) ? ty : (1.0f - ty)) * OUT_SCALE;
        if (!val) cf = 0.0f;
        int djs = val ? dj : 0;

        int k = k00 + ((b & 2) << 1) + (b & 1);
        const uint4* p = reinterpret_cast<const uint4*>(
            g_Yh + (size_t)k * kstride + (size_t)djs * 16 + s * 8);
        uint4 Y = *p;

        float2 f0 = h2f(Y.x), f1 = h2f(Y.y), f2 = h2f(Y.z), f3 = h2f(Y.w);
        float m0 = cf * f0.x, m1 = cf * f0.y;
        float m2 = cf * f1.x, m3 = cf * f1.y;
        float m4 = cf * f2.x, m5 = cf * f2.y;
        float m6 = cf * f3.x, m7 = cf * f3.y;

        float s0_ = keep1 ? m4 : m0;
        float s1_ = keep1 ? m5 : m1;
        float s2_ = keep1 ? m6 : m2;
        float s3_ = keep1 ? m7 : m3;
        float p0 = (keep1 ? m0 : m4) + __shfl_xor_sync(FULL, s0_, 2);
        float p1 = (keep1 ? m1 : m5) + __shfl_xor_sync(FULL, s1_, 2);
        float p2 = (keep1 ? m2 : m6) + __shfl_xor_sync(FULL, s2_, 2);
        float p3 = (keep1 ? m3 : m7) + __shfl_xor_sync(FULL, s3_, 2);

        float t0 = keep2 ? p2 : p0;
        float t1 = keep2 ? p3 : p1;
        float q0 = (keep2 ? p0 : p2) + __shfl_xor_sync(FULL, t0, 4);
        float q1 = (keep2 ? p1 : p3) + __shfl_xor_sync(FULL, t1, 4);

        if (val) {
            int idx = s * 8 + (b & 1) * 4 + ((b >> 1) & 1) * 2;
            float* ob = out + (size_t)di * 16 + idx;
            asm volatile("red.global.add.v2.f32 [%0], {%1, %2};"
                         :: "l"(ob), "f"(q0), "f"(q1) : "memory");
        }
    }
}

// Aligns ncu capture (-s 5 -c 1) onto stage1 (4 launches/call)
__global__ void k_dummy() {}

extern "C" void kernel_launch(void* const* d_in, const int* in_sizes, int n_in,
                              void* d_out, int out_size) {
    const float*  x  = (const float*)d_in[0];    // [N, 16] f32
    const float2* ea = (const float2*)d_in[1];   // [E, 2]  f32
    const float*  W  = (const float*)d_in[2];    // [16,16,16] f32
    const int*    ei = (const int*)d_in[3];      // [E] int32
    const int*    ej = (const int*)d_in[4];      // [E] int32
    float* out = (float*)d_out;

    int n_nodes = in_sizes[0] / F_DIM;
    int n_edges = in_sizes[1] / 2;

    cudaMemsetAsync(d_out, 0, (size_t)out_size * sizeof(float), 0);

    stage1_cols<<<(n_nodes + 63) / 64, 256>>>(x, W, n_nodes);

    int s2_blocks = (n_edges + 127) / 128;
    stage2_coop<<<s2_blocks, 256>>>(ea, ei, ej, out, n_nodes, n_edges);
    k_dummy<<<1, 32>>>();
}